// round 8
// baseline (speedup 1.0000x reference)
#include <cuda_runtime.h>
#include <cuda_fp16.h>
#include <math.h>

// Problem dims (fixed by the reference)
#define Bq 32
#define Tq 2048
#define Dq 512
#define Uq 512

// Scratch (no device allocation allowed -> __device__ globals)
__device__ float  g_uh[Bq * Uq];        // hidden@Uk + Ub + Wb  (per b,u bias)
__device__ float  g_lp[2 * Bq * Tq];    // partial logits per N-half (no atomics)
__device__ __half g_wkh[Uq * Dq];       // Wk^T as half, [u][d] (B operand, K-contiguous)

// ---------------- helpers ----------------
__device__ __forceinline__ unsigned smem_u32(const void* p) {
    unsigned a;
    asm("{ .reg .u64 t; cvta.to.shared.u64 t, %1; cvt.u32.u64 %0, t; }" : "=r"(a) : "l"(p));
    return a;
}
__device__ __forceinline__ void cpasync16(unsigned dst, const void* src) {
    asm volatile("cp.async.cg.shared.global [%0], [%1], 16;" :: "r"(dst), "l"(src));
}
__device__ __forceinline__ unsigned h2tanh(unsigned x) {   // MUFU.TANH on 2 halves
    unsigned r;
    asm("tanh.approx.f16x2 %0, %1;" : "=r"(r) : "r"(x));
    return r;
}
__device__ __forceinline__ void ldmx4(unsigned* r, unsigned addr) {
    asm volatile("ldmatrix.sync.aligned.m8n8.x4.shared.b16 {%0,%1,%2,%3}, [%4];"
                 : "=r"(r[0]), "=r"(r[1]), "=r"(r[2]), "=r"(r[3]) : "r"(addr));
}
__device__ __forceinline__ void mma_f16(float4& d, const unsigned* a,
                                        unsigned b0, unsigned b1) {
    asm volatile(
        "mma.sync.aligned.m16n8k16.row.col.f32.f16.f16.f32 "
        "{%0,%1,%2,%3}, {%4,%5,%6,%7}, {%8,%9}, {%0,%1,%2,%3};"
        : "+f"(d.x), "+f"(d.y), "+f"(d.z), "+f"(d.w)
        : "r"(a[0]), "r"(a[1]), "r"(a[2]), "r"(a[3]), "r"(b0), "r"(b1));
}

// ---------------------------------------------------------------------------
// Kernel 0a: g_uh[b,u] = hidden@Uk + Ub + Wb
// ---------------------------------------------------------------------------
__global__ void uh_kernel(const float* __restrict__ hidden,
                          const float* __restrict__ Uk,
                          const float* __restrict__ Ub,
                          const float* __restrict__ Wb) {
    int u = blockIdx.x * blockDim.x + threadIdx.x;
    int b = blockIdx.y;
    float acc = Ub[u] + Wb[u];
    const float* h = hidden + b * 512;
    #pragma unroll 8
    for (int k = 0; k < 512; k++)
        acc = fmaf(h[k], Uk[k * Uq + u], acc);
    g_uh[b * Uq + u] = acc;
}

// ---------------------------------------------------------------------------
// Kernel 0b: g_wkh[u][d] = half(Wk[d][u])
// ---------------------------------------------------------------------------
__global__ void wkh_kernel(const float* __restrict__ Wk) {
    __shared__ float t[32][33];
    int bu = blockIdx.x * 32, bd = blockIdx.y * 32;
    int tx = threadIdx.x, ty = threadIdx.y;       // 32 x 8
    #pragma unroll
    for (int i = 0; i < 32; i += 8)
        t[ty + i][tx] = Wk[(bd + ty + i) * Uq + bu + tx];   // t[d][u]
    __syncthreads();
    #pragma unroll
    for (int i = 0; i < 32; i += 8)
        g_wkh[(bu + ty + i) * Dq + bd + tx] = __float2half(t[tx][ty + i]);
}

// ---------------------------------------------------------------------------
// Kernel 1 (hot): partial logits via fp16 mma.sync m16n8k16 + ldmatrix.
// CTA: BM=64 rows x NPC=256 cols (one N-half; blockIdx.y selects half).
// 8 warps; warp w covers m64 x n32. acc float4[4][4] = 64 regs -> occ 2.
// B: 3-stage cp.async pipeline; A: reg double-buffer -> half smem (2 bufs).
// ONE __syncthreads per stage: all smem writes for future stages are issued
// after the top-of-iter barrier, so reuse distances (A:2, B:3) are safe.
// ---------------------------------------------------------------------------
#define BM 64
#define NPC 256
#define KS 32
#define NSTG (Dq / KS)          // 16 stages, 2 k16-steps each
#define ROWB 80                 // padded row pitch in bytes (40 halves)
#define ABUF (BM * ROWB)        // 5120
#define BBUF (NPC * ROWB)       // 20480

#define SM_A    0                       // 2 x ABUF  = 10240
#define SM_B    (2 * ABUF)              // 3 x BBUF  = 61440
#define SM_UH   (SM_B + 3 * BBUF)       // 71680  (256 floats)
#define SM_VK   (SM_UH + 1024)          // 72704  (256 floats)
#define SM_RED  (SM_VK + 1024)          // 73728  (64 floats)
#define SM_TOT  (SM_RED + 256 + 128)    // 74112 bytes -> 2 CTAs/SM

__global__ __launch_bounds__(256, 2)
void logits_kernel(const float* __restrict__ features,
                   const float* __restrict__ Vk) {
    extern __shared__ char smem[];
    const unsigned sb = smem_u32(smem);
    const int tid = threadIdx.x, lane = tid & 31, wid = tid >> 5;
    const int n0w = wid * 32;                   // warp's N offset within the half
    const int nh  = blockIdx.y;                 // which N-half (0/1)
    const long row0 = (long)blockIdx.x * BM;
    const int b = (int)(row0 >> 11);

    float* uhs = (float*)(smem + SM_UH);
    float* vks = (float*)(smem + SM_VK);
    float* red = (float*)(smem + SM_RED);

    if (tid < NPC) {
        uhs[tid] = g_uh[b * Uq + nh * NPC + tid];
        vks[tid] = Vk[nh * NPC + tid];
    }
    if (tid < BM) red[tid] = 0.f;

    const int ar_r   = tid >> 2;                // A row 0..63
    const int ar_k4a = (tid & 3) * 2;           // two consecutive float4 slots
    const int lr = lane & 7, sect = lane >> 3;  // ldmatrix lane addressing

    float4 acc[4][4];
    #pragma unroll
    for (int mi = 0; mi < 4; mi++)
        #pragma unroll
        for (int nt = 0; nt < 4; nt++) acc[mi][nt] = make_float4(0.f, 0.f, 0.f, 0.f);

    float4 ar[2][2];    // A global->reg double buffer

    auto loadA = [&](int s, int pb) {
        #pragma unroll
        for (int i = 0; i < 2; i++)
            ar[pb][i] = *reinterpret_cast<const float4*>(
                features + (row0 + ar_r) * Dq + s * KS + (ar_k4a + i) * 4);
    };
    auto storeA = [&](int s) {
        const int pb = s & 1;
        #pragma unroll
        for (int i = 0; i < 2; i++) {
            float4 v = ar[pb][i];
            __half2 h0 = __floats2half2_rn(v.x, v.y);
            __half2 h1 = __floats2half2_rn(v.z, v.w);
            uint2 u = make_uint2(*reinterpret_cast<unsigned*>(&h0),
                                 *reinterpret_cast<unsigned*>(&h1));
            *reinterpret_cast<uint2*>(smem + SM_A + (s & 1) * ABUF +
                                      ar_r * ROWB + (ar_k4a + i) * 8) = u;
        }
    };
    auto fillB = [&](int s) {
        const unsigned bb = sb + SM_B + (s % 3) * BBUF;
        const __half* src = g_wkh + (long)(nh * NPC) * Dq + s * KS;
        #pragma unroll
        for (int i = 0; i < 4; i++) {
            int idx = tid + i * 256;            // 0..1023
            int n = idx >> 2, c = idx & 3;
            cpasync16(bb + (unsigned)(n * ROWB + c * 16), src + n * Dq + c * 8);
        }
    };

    // prologue
    loadA(0, 0);
    loadA(1, 1);
    storeA(0);
    fillB(0); asm volatile("cp.async.commit_group;");
    fillB(1); asm volatile("cp.async.commit_group;");

    for (int s = 0; s < NSTG; s++) {
        if (s + 1 < NSTG) asm volatile("cp.async.wait_group 1;");
        else              asm volatile("cp.async.wait_group 0;");
        __syncthreads();   // B(s) visible; everyone done with stage s-1 reads

        if (s + 2 < NSTG) { fillB(s + 2); asm volatile("cp.async.commit_group;"); }
        if (s + 1 < NSTG) storeA(s + 1);
        if (s + 2 < NSTG) loadA(s + 2, s & 1);

        const unsigned ab = sb + SM_A + (s & 1) * ABUF;
        const unsigned bb = sb + SM_B + (s % 3) * BBUF;
        #pragma unroll
        for (int k16 = 0; k16 < 2; k16++) {
            const int kb = k16 * 16;            // halves offset within stage row
            unsigned af[4][4], bf[2][4];
            #pragma unroll
            for (int mi = 0; mi < 4; mi++)
                ldmx4(af[mi], ab + (unsigned)((mi * 16 + (sect & 1) * 8 + lr) * ROWB
                                              + (kb + (sect >> 1) * 8) * 2));
            #pragma unroll
            for (int nj = 0; nj < 2; nj++)
                ldmx4(bf[nj], bb + (unsigned)((n0w + nj * 16 + (sect >> 1) * 8 + lr) * ROWB
                                              + (kb + (sect & 1) * 8) * 2));
            #pragma unroll
            for (int mi = 0; mi < 4; mi++)
                #pragma unroll
                for (int nj = 0; nj < 2; nj++) {
                    mma_f16(acc[mi][2 * nj],     af[mi], bf[nj][0], bf[nj][1]);
                    mma_f16(acc[mi][2 * nj + 1], af[mi], bf[nj][2], bf[nj][3]);
                }
        }
    }

    // ---- epilogue: x = d + uh; tanh (f16x2); rowsum += Vk * tanh ----
    const int g = lane >> 2, t = lane & 3;
    float rs[8];
    #pragma unroll
    for (int i = 0; i < 8; i++) rs[i] = 0.f;
    #pragma unroll
    for (int mi = 0; mi < 4; mi++)
        #pragma unroll
        for (int nt = 0; nt < 4; nt++) {
            const int n = n0w + nt * 8 + 2 * t;
            float uh0 = uhs[n], uh1 = uhs[n + 1];
            float vk0 = vks[n], vk1 = vks[n + 1];
            float4 d = acc[mi][nt];
            __half2 h0 = __floats2half2_rn(d.x + uh0, d.y + uh1);
            unsigned t0 = h2tanh(*reinterpret_cast<unsigned*>(&h0));
            float2 f0 = __half22float2(*reinterpret_cast<__half2*>(&t0));
            rs[mi * 2]     = fmaf(vk0, f0.x, fmaf(vk1, f0.y, rs[mi * 2]));
            __half2 h1 = __floats2half2_rn(d.z + uh0, d.w + uh1);
            unsigned t1 = h2tanh(*reinterpret_cast<unsigned*>(&h1));
            float2 f1 = __half22float2(*reinterpret_cast<__half2*>(&t1));
            rs[mi * 2 + 1] = fmaf(vk0, f1.x, fmaf(vk1, f1.y, rs[mi * 2 + 1]));
        }
    #pragma unroll
    for (int i = 0; i < 8; i++) {
        rs[i] += __shfl_xor_sync(0xffffffffu, rs[i], 1);
        rs[i] += __shfl_xor_sync(0xffffffffu, rs[i], 2);
    }
    __syncthreads();   // red[] init + all prior smem traffic done
    if (t == 0) {
        #pragma unroll
        for (int mi = 0; mi < 4; mi++) {
            atomicAdd(&red[mi * 16 + g],     rs[mi * 2]);   // 8 warps fold (smem atomic)
            atomicAdd(&red[mi * 16 + 8 + g], rs[mi * 2 + 1]);
        }
    }
    __syncthreads();
    if (tid < BM) g_lp[(long)nh * (Bq * Tq) + row0 + tid] = red[tid];
}

// ---------------------------------------------------------------------------
// Kernel 2: softmax over T per batch (sums the two N-half partials);
// writes weights to d_out; zeroes ctx for context accumulation.
// ---------------------------------------------------------------------------
__global__ void softmax_kernel(float* __restrict__ out_w, float* __restrict__ ctx) {
    const int b = blockIdx.x;
    const int tid = threadIdx.x;   // 256
    __shared__ float sm[256];
    const float* l0 = g_lp + b * Tq;
    const float* l1 = g_lp + (Bq * Tq) + b * Tq;

    ctx[b * Dq + tid] = 0.f;
    ctx[b * Dq + 256 + tid] = 0.f;

    float mx = -1e30f;
    for (int t = tid; t < Tq; t += 256) mx = fmaxf(mx, l0[t] + l1[t]);
    sm[tid] = mx; __syncthreads();
    for (int s = 128; s > 0; s >>= 1) {
        if (tid < s) sm[tid] = fmaxf(sm[tid], sm[tid + s]);
        __syncthreads();
    }
    mx = sm[0]; __syncthreads();

    float sum = 0.f;
    for (int t = tid; t < Tq; t += 256) sum += expf(l0[t] + l1[t] - mx);
    sm[tid] = sum; __syncthreads();
    for (int s = 128; s > 0; s >>= 1) {
        if (tid < s) sm[tid] += sm[tid + s];
        __syncthreads();
    }
    float inv = 1.f / sm[0];

    for (int t = tid; t < Tq; t += 256)
        out_w[b * Tq + t] = expf(l0[t] + l1[t] - mx) * inv;
}

// ---------------------------------------------------------------------------
// Kernel 3: context[b,d] = sum_t w[b,t] * features[b,t,d]
// ---------------------------------------------------------------------------
#define TCHUNK 128
__global__ __launch_bounds__(256, 8)
void context_kernel(const float* __restrict__ features,
                    const float* __restrict__ w,
                    float* __restrict__ ctx) {
    __shared__ float ws[TCHUNK];
    const int b  = blockIdx.y;
    const int t0 = blockIdx.x * TCHUNK;
    const int tid = threadIdx.x;
    const int d4 = tid & 127;
    const int tp = tid >> 7;

    if (tid < TCHUNK) ws[tid] = w[b * Tq + t0 + tid];
    __syncthreads();

    const float* fb = features + (long)b * Tq * Dq + (long)t0 * Dq + d4 * 4;
    float4 acc = make_float4(0.f, 0.f, 0.f, 0.f);
    #pragma unroll 4
    for (int i = tp; i < TCHUNK; i += 2) {
        float  wt = ws[i];
        float4 v  = *reinterpret_cast<const float4*>(fb + (long)i * Dq);
        acc.x = fmaf(wt, v.x, acc.x);
        acc.y = fmaf(wt, v.y, acc.y);
        acc.z = fmaf(wt, v.z, acc.z);
        acc.w = fmaf(wt, v.w, acc.w);
    }
    float* dst = ctx + b * Dq + d4 * 4;
    atomicAdd(dst + 0, acc.x);
    atomicAdd(dst + 1, acc.y);
    atomicAdd(dst + 2, acc.z);
    atomicAdd(dst + 3, acc.w);
}

// ---------------------------------------------------------------------------
extern "C" void kernel_launch(void* const* d_in, const int* in_sizes, int n_in,
                              void* d_out, int out_size) {
    const float* features = (const float*)d_in[0];  // [B,T,D]
    const float* hidden   = (const float*)d_in[1];  // [B,H]
    const float* Wk       = (const float*)d_in[2];  // [D,U]
    const float* Wb       = (const float*)d_in[3];  // [U]
    const float* Uk       = (const float*)d_in[4];  // [H,U]
    const float* Ub       = (const float*)d_in[5];  // [U]
    const float* Vk       = (const float*)d_in[6];  // [U,1]
    // d_in[7] = Vb [1]: uniform logit shift -> softmax-invariant -> unused.

    float* out  = (float*)d_out;
    float* ctx  = out;               // context_vector [B, D]  (tuple output 0)
    float* attw = out + Bq * Dq;     // attention_weights [B, T, 1] (tuple output 1)

    cudaFuncSetAttribute(logits_kernel,
                         cudaFuncAttributeMaxDynamicSharedMemorySize, SM_TOT);

    uh_kernel<<<dim3(Uq / 128, Bq), 128>>>(hidden, Uk, Ub, Wb);
    wkh_kernel<<<dim3(16, 16), dim3(32, 8)>>>(Wk);
    logits_kernel<<<dim3((Bq * Tq) / BM, 2), 256, SM_TOT>>>(features, Vk);
    softmax_kernel<<<Bq, 256>>>(attw, ctx);
    context_kernel<<<dim3(Tq / TCHUNK, Bq), 256>>>(features, attw, ctx);
}

// round 9
// speedup vs baseline: 1.2487x; 1.2487x over previous
#include <cuda_runtime.h>
#include <cuda_fp16.h>
#include <math.h>

// Problem dims (fixed by the reference)
#define Bq 32
#define Tq 2048
#define Dq 512
#define Uq 512

// Scratch (no device allocation allowed -> __device__ globals)
__device__ float  g_uh[Bq * Uq];      // hidden@Uk + Ub + Wb  (per b,u bias)
__device__ float  g_logits[Bq * Tq];  // pre-softmax logits (Vb dropped: softmax-invariant)
__device__ __half g_wkh[Uq * Dq];     // Wk^T as half, [u][d] (B operand, K-contiguous)

// ---------------- helpers ----------------
__device__ __forceinline__ unsigned smem_u32(const void* p) {
    unsigned a;
    asm("{ .reg .u64 t; cvta.to.shared.u64 t, %1; cvt.u32.u64 %0, t; }" : "=r"(a) : "l"(p));
    return a;
}
__device__ __forceinline__ void cpasync16(unsigned dst, const void* src) {
    asm volatile("cp.async.cg.shared.global [%0], [%1], 16;" :: "r"(dst), "l"(src));
}
__device__ __forceinline__ unsigned h2tanh(unsigned x) {   // MUFU.TANH on 2 halves
    unsigned r;
    asm("tanh.approx.f16x2 %0, %1;" : "=r"(r) : "r"(x));
    return r;
}
__device__ __forceinline__ void ldmx4(unsigned* r, unsigned addr) {
    asm volatile("ldmatrix.sync.aligned.m8n8.x4.shared.b16 {%0,%1,%2,%3}, [%4];"
                 : "=r"(r[0]), "=r"(r[1]), "=r"(r[2]), "=r"(r[3]) : "r"(addr));
}
__device__ __forceinline__ void mma_f16(float4& d, const unsigned* a,
                                        unsigned b0, unsigned b1) {
    asm volatile(
        "mma.sync.aligned.m16n8k16.row.col.f32.f16.f16.f32 "
        "{%0,%1,%2,%3}, {%4,%5,%6,%7}, {%8,%9}, {%0,%1,%2,%3};"
        : "+f"(d.x), "+f"(d.y), "+f"(d.z), "+f"(d.w)
        : "r"(a[0]), "r"(a[1]), "r"(a[2]), "r"(a[3]), "r"(b0), "r"(b1));
}

// ---------------------------------------------------------------------------
// Kernel 0a: g_uh[b,u] = hidden@Uk + Ub + Wb
// ---------------------------------------------------------------------------
__global__ void uh_kernel(const float* __restrict__ hidden,
                          const float* __restrict__ Uk,
                          const float* __restrict__ Ub,
                          const float* __restrict__ Wb) {
    int u = blockIdx.x * blockDim.x + threadIdx.x;
    int b = blockIdx.y;
    float acc = Ub[u] + Wb[u];
    const float* h = hidden + b * 512;
    #pragma unroll 8
    for (int k = 0; k < 512; k++)
        acc = fmaf(h[k], Uk[k * Uq + u], acc);
    g_uh[b * Uq + u] = acc;
}

// ---------------------------------------------------------------------------
// Kernel 0b: g_wkh[u][d] = half(Wk[d][u])
// ---------------------------------------------------------------------------
__global__ void wkh_kernel(const float* __restrict__ Wk) {
    __shared__ float t[32][33];
    int bu = blockIdx.x * 32, bd = blockIdx.y * 32;
    int tx = threadIdx.x, ty = threadIdx.y;       // 32 x 8
    #pragma unroll
    for (int i = 0; i < 32; i += 8)
        t[ty + i][tx] = Wk[(bd + ty + i) * Uq + bu + tx];   // t[d][u]
    __syncthreads();
    #pragma unroll
    for (int i = 0; i < 32; i += 8)
        g_wkh[(bu + ty + i) * Dq + bd + tx] = __float2half(t[tx][ty + i]);
}

// ---------------------------------------------------------------------------
// Kernel 1 (hot): logits via fp16 mma.sync m16n8k16 + ldmatrix.
// R7 shape: CTA = BM=64 rows x N=512, 8 warps, warp tile m64 x n64,
// acc float4[4][8] = 128 regs, occ 1.
// R9 change vs R7: ONE __syncthreads per stage; B pipeline 3-deep, A 2-deep.
// All smem writes for stages s+1/s+2 are issued after the top-of-iter barrier,
// so write targets were last read at stage s-1 (complete before the barrier).
// ---------------------------------------------------------------------------
#define BM 64
#define KS 32
#define NSTG (Dq / KS)          // 16 stages, 2 k16-steps each
#define ROWB 80                 // padded row pitch in bytes (40 halves)
#define ABUF (BM * ROWB)        // 5120
#define BBUF (Uq * ROWB)        // 40960

#define SM_A    0                       // 2 x ABUF  = 10240
#define SM_B    (2 * ABUF)              // 3 x BBUF  = 122880
#define SM_UH   (SM_B + 3 * BBUF)       // 133120
#define SM_VK   (SM_UH + 2048)          // 135168
#define SM_RED  (SM_VK + 2048)          // 137216
#define SM_TOT  (SM_RED + 256 + 128)    // 137600 bytes (occ 1)

__global__ __launch_bounds__(256, 1)
void logits_kernel(const float* __restrict__ features,
                   const float* __restrict__ Vk) {
    extern __shared__ char smem[];
    const unsigned sb = smem_u32(smem);
    const int tid = threadIdx.x, lane = tid & 31, wid = tid >> 5;
    const int n0w = wid * 64;                   // warp's N offset
    const long row0 = (long)blockIdx.x * BM;
    const int b = (int)(row0 >> 11);

    float* uhs = (float*)(smem + SM_UH);
    float* vks = (float*)(smem + SM_VK);
    float* red = (float*)(smem + SM_RED);

    for (int i = tid; i < Uq; i += 256) { uhs[i] = g_uh[b * Uq + i]; vks[i] = Vk[i]; }
    if (tid < BM) red[tid] = 0.f;

    const int ar_r   = tid >> 2;                // A row 0..63
    const int ar_k4a = (tid & 3) * 2;           // two consecutive float4 slots
    const int lr = lane & 7, sect = lane >> 3;  // ldmatrix lane addressing

    float4 acc[4][8];
    #pragma unroll
    for (int mi = 0; mi < 4; mi++)
        #pragma unroll
        for (int nt = 0; nt < 8; nt++) acc[mi][nt] = make_float4(0.f, 0.f, 0.f, 0.f);

    float4 ar[2][2];    // A global->reg double buffer

    auto loadA = [&](int s, int pb) {
        #pragma unroll
        for (int i = 0; i < 2; i++)
            ar[pb][i] = *reinterpret_cast<const float4*>(
                features + (row0 + ar_r) * Dq + s * KS + (ar_k4a + i) * 4);
    };
    auto storeA = [&](int s) {
        const int pb = s & 1;
        #pragma unroll
        for (int i = 0; i < 2; i++) {
            float4 v = ar[pb][i];
            __half2 h0 = __floats2half2_rn(v.x, v.y);
            __half2 h1 = __floats2half2_rn(v.z, v.w);
            uint2 u = make_uint2(*reinterpret_cast<unsigned*>(&h0),
                                 *reinterpret_cast<unsigned*>(&h1));
            *reinterpret_cast<uint2*>(smem + SM_A + (s & 1) * ABUF +
                                      ar_r * ROWB + (ar_k4a + i) * 8) = u;
        }
    };
    auto fillB = [&](int s) {
        const unsigned bb = sb + SM_B + (s % 3) * BBUF;
        const __half* src = g_wkh + s * KS;
        #pragma unroll
        for (int i = 0; i < 8; i++) {
            int idx = tid + i * 256;            // 0..2047
            int n = idx >> 2, c = idx & 3;
            cpasync16(bb + (unsigned)(n * ROWB + c * 16), src + n * Dq + c * 8);
        }
    };

    // prologue: A for stages 0,1 in regs; A(0) in smem; B(0),B(1) in flight
    loadA(0, 0);
    loadA(1, 1);
    storeA(0);
    fillB(0); asm volatile("cp.async.commit_group;");
    fillB(1); asm volatile("cp.async.commit_group;");

    for (int s = 0; s < NSTG; s++) {
        if (s + 1 < NSTG) asm volatile("cp.async.wait_group 1;");
        else              asm volatile("cp.async.wait_group 0;");
        __syncthreads();   // B(s)+A(s) visible; all warps done reading stage s-1

        if (s + 2 < NSTG) { fillB(s + 2); asm volatile("cp.async.commit_group;"); }
        if (s + 1 < NSTG) storeA(s + 1);
        if (s + 2 < NSTG) loadA(s + 2, s & 1);

        const unsigned ab = sb + SM_A + (s & 1) * ABUF;
        const unsigned bb = sb + SM_B + (s % 3) * BBUF;
        #pragma unroll
        for (int k16 = 0; k16 < 2; k16++) {
            const int kb = k16 * 16;            // halves offset within stage row
            unsigned af[4][4], bf[4][4];
            // A frags: (m0:8,k0:8),(m8:16,k0:8),(m0:8,k8:16),(m8:16,k8:16)
            #pragma unroll
            for (int mi = 0; mi < 4; mi++)
                ldmx4(af[mi], ab + (unsigned)((mi * 16 + (sect & 1) * 8 + lr) * ROWB
                                              + (kb + (sect >> 1) * 8) * 2));
            // B frags: (n0:8,k0:8),(n0:8,k8:16),(n8:16,k0:8),(n8:16,k8:16)
            #pragma unroll
            for (int nj = 0; nj < 4; nj++)
                ldmx4(bf[nj], bb + (unsigned)((n0w + nj * 16 + (sect >> 1) * 8 + lr) * ROWB
                                              + (kb + (sect & 1) * 8) * 2));
            #pragma unroll
            for (int mi = 0; mi < 4; mi++)
                #pragma unroll
                for (int nj = 0; nj < 4; nj++) {
                    mma_f16(acc[mi][2 * nj],     af[mi], bf[nj][0], bf[nj][1]);
                    mma_f16(acc[mi][2 * nj + 1], af[mi], bf[nj][2], bf[nj][3]);
                }
        }
    }

    // ---- epilogue: x = d + uh; tanh (f16x2); rowsum += Vk * tanh ----
    const int g = lane >> 2, t = lane & 3;
    float rs[8];
    #pragma unroll
    for (int i = 0; i < 8; i++) rs[i] = 0.f;
    #pragma unroll
    for (int mi = 0; mi < 4; mi++)
        #pragma unroll
        for (int nt = 0; nt < 8; nt++) {
            const int n = n0w + nt * 8 + 2 * t;
            float uh0 = uhs[n], uh1 = uhs[n + 1];
            float vk0 = vks[n], vk1 = vks[n + 1];
            float4 d = acc[mi][nt];
            __half2 h0 = __floats2half2_rn(d.x + uh0, d.y + uh1);
            unsigned t0 = h2tanh(*reinterpret_cast<unsigned*>(&h0));
            float2 f0 = __half22float2(*reinterpret_cast<__half2*>(&t0));
            rs[mi * 2]     = fmaf(vk0, f0.x, fmaf(vk1, f0.y, rs[mi * 2]));
            __half2 h1 = __floats2half2_rn(d.z + uh0, d.w + uh1);
            unsigned t1 = h2tanh(*reinterpret_cast<unsigned*>(&h1));
            float2 f1 = __half22float2(*reinterpret_cast<__half2*>(&t1));
            rs[mi * 2 + 1] = fmaf(vk0, f1.x, fmaf(vk1, f1.y, rs[mi * 2 + 1]));
        }
    #pragma unroll
    for (int i = 0; i < 8; i++) {
        rs[i] += __shfl_xor_sync(0xffffffffu, rs[i], 1);
        rs[i] += __shfl_xor_sync(0xffffffffu, rs[i], 2);
    }
    __syncthreads();
    if (t == 0) {
        #pragma unroll
        for (int mi = 0; mi < 4; mi++) {
            atomicAdd(&red[mi * 16 + g],     rs[mi * 2]);
            atomicAdd(&red[mi * 16 + 8 + g], rs[mi * 2 + 1]);
        }
    }
    __syncthreads();
    if (tid < BM) g_logits[row0 + tid] = red[tid];
}

// ---------------------------------------------------------------------------
// Kernel 2: softmax over T per batch -> weights to d_out; also zeroes ctx
// ---------------------------------------------------------------------------
__global__ void softmax_kernel(float* __restrict__ out_w, float* __restrict__ ctx) {
    const int b = blockIdx.x;
    const int tid = threadIdx.x;   // 256
    __shared__ float sm[256];
    const float* lg = g_logits + b * Tq;

    ctx[b * Dq + tid] = 0.f;
    ctx[b * Dq + 256 + tid] = 0.f;

    float mx = -1e30f;
    for (int t = tid; t < Tq; t += 256) mx = fmaxf(mx, lg[t]);
    sm[tid] = mx; __syncthreads();
    for (int s = 128; s > 0; s >>= 1) {
        if (tid < s) sm[tid] = fmaxf(sm[tid], sm[tid + s]);
        __syncthreads();
    }
    mx = sm[0]; __syncthreads();

    float sum = 0.f;
    for (int t = tid; t < Tq; t += 256) sum += expf(lg[t] - mx);
    sm[tid] = sum; __syncthreads();
    for (int s = 128; s > 0; s >>= 1) {
        if (tid < s) sm[tid] += sm[tid + s];
        __syncthreads();
    }
    float inv = 1.f / sm[0];

    for (int t = tid; t < Tq; t += 256)
        out_w[b * Tq + t] = expf(lg[t] - mx) * inv;
}

// ---------------------------------------------------------------------------
// Kernel 3: context[b,d] = sum_t w[b,t] * features[b,t,d]
// ---------------------------------------------------------------------------
#define TCHUNK 128
__global__ __launch_bounds__(256, 8)
void context_kernel(const float* __restrict__ features,
                    const float* __restrict__ w,
                    float* __restrict__ ctx) {
    __shared__ float ws[TCHUNK];
    const int b  = blockIdx.y;
    const int t0 = blockIdx.x * TCHUNK;
    const int tid = threadIdx.x;
    const int d4 = tid & 127;
    const int tp = tid >> 7;

    if (tid < TCHUNK) ws[tid] = w[b * Tq + t0 + tid];
    __syncthreads();

    const float* fb = features + (long)b * Tq * Dq + (long)t0 * Dq + d4 * 4;
    float4 acc = make_float4(0.f, 0.f, 0.f, 0.f);
    #pragma unroll 4
    for (int i = tp; i < TCHUNK; i += 2) {
        float  wt = ws[i];
        float4 v  = *reinterpret_cast<const float4*>(fb + (long)i * Dq);
        acc.x = fmaf(wt, v.x, acc.x);
        acc.y = fmaf(wt, v.y, acc.y);
        acc.z = fmaf(wt, v.z, acc.z);
        acc.w = fmaf(wt, v.w, acc.w);
    }
    float* dst = ctx + b * Dq + d4 * 4;
    atomicAdd(dst + 0, acc.x);
    atomicAdd(dst + 1, acc.y);
    atomicAdd(dst + 2, acc.z);
    atomicAdd(dst + 3, acc.w);
}

// ---------------------------------------------------------------------------
extern "C" void kernel_launch(void* const* d_in, const int* in_sizes, int n_in,
                              void* d_out, int out_size) {
    const float* features = (const float*)d_in[0];  // [B,T,D]
    const float* hidden   = (const float*)d_in[1];  // [B,H]
    const float* Wk       = (const float*)d_in[2];  // [D,U]
    const float* Wb       = (const float*)d_in[3];  // [U]
    const float* Uk       = (const float*)d_in[4];  // [H,U]
    const float* Ub       = (const float*)d_in[5];  // [U]
    const float* Vk       = (const float*)d_in[6];  // [U,1]
    // d_in[7] = Vb [1]: uniform logit shift -> softmax-invariant -> unused.

    float* out  = (float*)d_out;
    float* ctx  = out;               // context_vector [B, D]  (tuple output 0)
    float* attw = out + Bq * Dq;     // attention_weights [B, T, 1] (tuple output 1)

    cudaFuncSetAttribute(logits_kernel,
                         cudaFuncAttributeMaxDynamicSharedMemorySize, SM_TOT);

    uh_kernel<<<dim3(Uq / 128, Bq), 128>>>(hidden, Uk, Ub, Wb);
    wkh_kernel<<<dim3(16, 16), dim3(32, 8)>>>(Wk);
    logits_kernel<<<(Bq * Tq) / BM, 256, SM_TOT>>>(features, Vk);
    softmax_kernel<<<Bq, 256>>>(attw, ctx);
    context_kernel<<<dim3(Tq / TCHUNK, Bq), 256>>>(features, attw, ctx);
}

// round 10
// speedup vs baseline: 1.7732x; 1.4200x over previous
#include <cuda_runtime.h>
#include <cuda_fp16.h>
#include <math.h>

// Problem dims (fixed by the reference)
#define Bq 32
#define Tq 2048
#define Dq 512
#define Uq 512

// Scratch (no device allocation allowed -> __device__ globals)
__device__ float  g_uh[Bq * Uq];      // hidden@Uk + Ub + Wb  (per b,u bias)
__device__ float  g_logits[Bq * Tq];  // pre-softmax logits (Vb dropped: softmax-invariant)
__device__ __half g_wkh[Uq * Dq];     // Wk^T as half, [u][d] (B operand, K-contiguous)

// ---------------- helpers ----------------
__device__ __forceinline__ unsigned smem_u32(const void* p) {
    unsigned a;
    asm("{ .reg .u64 t; cvta.to.shared.u64 t, %1; cvt.u32.u64 %0, t; }" : "=r"(a) : "l"(p));
    return a;
}
__device__ __forceinline__ void cpasync16(unsigned dst, const void* src) {
    asm volatile("cp.async.cg.shared.global [%0], [%1], 16;" :: "r"(dst), "l"(src));
}
__device__ __forceinline__ unsigned h2tanh(unsigned x) {   // MUFU.TANH on 2 halves
    unsigned r;
    asm("tanh.approx.f16x2 %0, %1;" : "=r"(r) : "r"(x));
    return r;
}
__device__ __forceinline__ unsigned h2add(unsigned a, unsigned b) {
    unsigned r;
    asm("add.f16x2 %0, %1, %2;" : "=r"(r) : "r"(a), "r"(b));
    return r;
}
__device__ __forceinline__ void ldmx4(unsigned* r, unsigned addr) {
    asm volatile("ldmatrix.sync.aligned.m8n8.x4.shared.b16 {%0,%1,%2,%3}, [%4];"
                 : "=r"(r[0]), "=r"(r[1]), "=r"(r[2]), "=r"(r[3]) : "r"(addr));
}
// fp16-accumulate MMA: C/D are 2 regs of f16x2
__device__ __forceinline__ void mma_f16a(unsigned& c0, unsigned& c1, const unsigned* a,
                                         unsigned b0, unsigned b1) {
    asm volatile(
        "mma.sync.aligned.m16n8k16.row.col.f16.f16.f16.f16 "
        "{%0,%1}, {%2,%3,%4,%5}, {%6,%7}, {%0,%1};"
        : "+r"(c0), "+r"(c1)
        : "r"(a[0]), "r"(a[1]), "r"(a[2]), "r"(a[3]), "r"(b0), "r"(b1));
}

// ---------------------------------------------------------------------------
// Kernel 0a: g_uh[b,u] = hidden@Uk + Ub + Wb
// ---------------------------------------------------------------------------
__global__ void uh_kernel(const float* __restrict__ hidden,
                          const float* __restrict__ Uk,
                          const float* __restrict__ Ub,
                          const float* __restrict__ Wb) {
    int u = blockIdx.x * blockDim.x + threadIdx.x;
    int b = blockIdx.y;
    float acc = Ub[u] + Wb[u];
    const float* h = hidden + b * 512;
    #pragma unroll 8
    for (int k = 0; k < 512; k++)
        acc = fmaf(h[k], Uk[k * Uq + u], acc);
    g_uh[b * Uq + u] = acc;
}

// ---------------------------------------------------------------------------
// Kernel 0b: g_wkh[u][d] = half(Wk[d][u])
// ---------------------------------------------------------------------------
__global__ void wkh_kernel(const float* __restrict__ Wk) {
    __shared__ float t[32][33];
    int bu = blockIdx.x * 32, bd = blockIdx.y * 32;
    int tx = threadIdx.x, ty = threadIdx.y;       // 32 x 8
    #pragma unroll
    for (int i = 0; i < 32; i += 8)
        t[ty + i][tx] = Wk[(bd + ty + i) * Uq + bu + tx];   // t[d][u]
    __syncthreads();
    #pragma unroll
    for (int i = 0; i < 32; i += 8)
        g_wkh[(bu + ty + i) * Dq + bd + tx] = __float2half(t[tx][ty + i]);
}

// ---------------------------------------------------------------------------
// Kernel 1 (hot): R7 structure EXACTLY (2-deep B, two syncs/stage), with the
// single change: f16-accumulate mma (acc = 2 regs/tile -> 64 regs) enabling
// __launch_bounds__(256,2) -> occupancy 2.
// CTA: BM=64 rows x N=512, 8 warps, warp tile m64 x n64.
// ---------------------------------------------------------------------------
#define BM 64
#define KS 32
#define NSTG (Dq / KS)          // 16 stages, 2 k16-steps each
#define ROWB 80                 // padded row pitch in bytes (40 halves)
#define ABUF (BM * ROWB)        // 5120
#define BBUF (Uq * ROWB)        // 40960

#define SM_A    0                       // 2 x ABUF = 10240
#define SM_B    10240                   // 2 x BBUF = 81920
#define SM_UH   (SM_B + 2 * BBUF)       // 92160  (256 half2 = 1KB used)
#define SM_VK   (SM_UH + 2048)          // 94208  (512 floats)
#define SM_RED  (SM_VK + 2048)          // 96256  (64 floats)
#define SM_TOT  (SM_RED + 256)          // 96512 bytes -> 2 CTAs/SM (193KB < 228KB)

__global__ __launch_bounds__(256, 2)
void logits_kernel(const float* __restrict__ features,
                   const float* __restrict__ Vk) {
    extern __shared__ char smem[];
    const unsigned sb = smem_u32(smem);
    const int tid = threadIdx.x, lane = tid & 31, wid = tid >> 5;
    const int n0w = wid * 64;                   // warp's N offset
    const long row0 = (long)blockIdx.x * BM;
    const int b = (int)(row0 >> 11);

    unsigned* uh2s = (unsigned*)(smem + SM_UH);     // 256 x half2
    float*    vks  = (float*)(smem + SM_VK);
    float*    red  = (float*)(smem + SM_RED);

    {
        __half2 h = __floats2half2_rn(g_uh[b * Uq + 2 * tid], g_uh[b * Uq + 2 * tid + 1]);
        uh2s[tid] = *reinterpret_cast<unsigned*>(&h);
        vks[tid] = Vk[tid];
        vks[tid + 256] = Vk[tid + 256];
    }
    if (tid < BM) red[tid] = 0.f;

    const int ar_r   = tid >> 2;                // A row 0..63
    const int ar_k4a = (tid & 3) * 2;           // two consecutive float4 slots
    const int lr = lane & 7, sect = lane >> 3;  // ldmatrix lane addressing

    unsigned acc16[4][8][2];                    // f16x2 accumulators (64 regs)
    #pragma unroll
    for (int mi = 0; mi < 4; mi++)
        #pragma unroll
        for (int nt = 0; nt < 8; nt++) { acc16[mi][nt][0] = 0u; acc16[mi][nt][1] = 0u; }

    float4 ar[2][2];    // A global->reg double buffer

    auto loadA = [&](int s, int pb) {
        #pragma unroll
        for (int i = 0; i < 2; i++)
            ar[pb][i] = *reinterpret_cast<const float4*>(
                features + (row0 + ar_r) * Dq + s * KS + (ar_k4a + i) * 4);
    };
    auto storeA = [&](int buf, int pb) {
        #pragma unroll
        for (int i = 0; i < 2; i++) {
            float4 v = ar[pb][i];
            __half2 h0 = __floats2half2_rn(v.x, v.y);
            __half2 h1 = __floats2half2_rn(v.z, v.w);
            uint2 u = make_uint2(*reinterpret_cast<unsigned*>(&h0),
                                 *reinterpret_cast<unsigned*>(&h1));
            *reinterpret_cast<uint2*>(smem + SM_A + buf * ABUF +
                                      ar_r * ROWB + (ar_k4a + i) * 8) = u;
        }
    };
    auto fillB = [&](int s, int buf) {
        const unsigned bb = sb + SM_B + buf * BBUF;
        #pragma unroll
        for (int i = 0; i < 8; i++) {
            int idx = tid + i * 256;            // 0..2047
            int n = idx >> 2, c = idx & 3;
            cpasync16(bb + (unsigned)(n * ROWB + c * 16),
                      g_wkh + n * Dq + s * KS + c * 8);
        }
    };

    loadA(0, 0);
    fillB(0, 0);
    asm volatile("cp.async.commit_group;");

    for (int s = 0; s < NSTG; s++) {
        const int buf = s & 1;
        if (s + 1 < NSTG) {
            fillB(s + 1, 1 - buf);
            asm volatile("cp.async.commit_group;");
            loadA(s + 1, 1 - buf);
        }
        storeA(buf, buf);
        if (s + 1 < NSTG) asm volatile("cp.async.wait_group 1;");
        else              asm volatile("cp.async.wait_group 0;");
        __syncthreads();

        const unsigned ab = sb + SM_A + buf * ABUF;
        const unsigned bb = sb + SM_B + buf * BBUF;
        #pragma unroll
        for (int k16 = 0; k16 < 2; k16++) {
            const int kb = k16 * 16;            // halves offset within stage row
            unsigned af[4][4], bf[4][4];
            // A frags: (m0:8,k0:8),(m8:16,k0:8),(m0:8,k8:16),(m8:16,k8:16)
            #pragma unroll
            for (int mi = 0; mi < 4; mi++)
                ldmx4(af[mi], ab + (unsigned)((mi * 16 + (sect & 1) * 8 + lr) * ROWB
                                              + (kb + (sect >> 1) * 8) * 2));
            // B frags: (n0:8,k0:8),(n0:8,k8:16),(n8:16,k0:8),(n8:16,k8:16)
            #pragma unroll
            for (int nj = 0; nj < 4; nj++)
                ldmx4(bf[nj], bb + (unsigned)((n0w + nj * 16 + (sect >> 1) * 8 + lr) * ROWB
                                              + (kb + (sect & 1) * 8) * 2));
            #pragma unroll
            for (int mi = 0; mi < 4; mi++)
                #pragma unroll
                for (int nj = 0; nj < 4; nj++) {
                    mma_f16a(acc16[mi][2 * nj][0],     acc16[mi][2 * nj][1],
                             af[mi], bf[nj][0], bf[nj][1]);
                    mma_f16a(acc16[mi][2 * nj + 1][0], acc16[mi][2 * nj + 1][1],
                             af[mi], bf[nj][2], bf[nj][3]);
                }
        }
        __syncthreads();
    }

    // ---- epilogue: x = acc + uh (f16x2); tanh (f16x2); rowsum += Vk * tanh ----
    const int g = lane >> 2, t = lane & 3;
    float rs[8];
    #pragma unroll
    for (int i = 0; i < 8; i++) rs[i] = 0.f;
    #pragma unroll
    for (int mi = 0; mi < 4; mi++)
        #pragma unroll
        for (int nt = 0; nt < 8; nt++) {
            const int n = n0w + nt * 8 + 2 * t;
            unsigned uh2 = uh2s[n >> 1];
            float vk0 = vks[n], vk1 = vks[n + 1];
            // c0: row g
            unsigned t0 = h2tanh(h2add(acc16[mi][nt][0], uh2));
            float2 f0 = __half22float2(*reinterpret_cast<__half2*>(&t0));
            rs[mi * 2]     = fmaf(vk0, f0.x, fmaf(vk1, f0.y, rs[mi * 2]));
            // c1: row g+8
            unsigned t1 = h2tanh(h2add(acc16[mi][nt][1], uh2));
            float2 f1 = __half22float2(*reinterpret_cast<__half2*>(&t1));
            rs[mi * 2 + 1] = fmaf(vk0, f1.x, fmaf(vk1, f1.y, rs[mi * 2 + 1]));
        }
    #pragma unroll
    for (int i = 0; i < 8; i++) {
        rs[i] += __shfl_xor_sync(0xffffffffu, rs[i], 1);
        rs[i] += __shfl_xor_sync(0xffffffffu, rs[i], 2);
    }
    if (t == 0) {
        #pragma unroll
        for (int mi = 0; mi < 4; mi++) {
            atomicAdd(&red[mi * 16 + g],     rs[mi * 2]);
            atomicAdd(&red[mi * 16 + 8 + g], rs[mi * 2 + 1]);
        }
    }
    __syncthreads();
    if (tid < BM) g_logits[row0 + tid] = red[tid];
}

// ---------------------------------------------------------------------------
// Kernel 2: softmax over T per batch -> weights to d_out; also zeroes ctx
// ---------------------------------------------------------------------------
__global__ void softmax_kernel(float* __restrict__ out_w, float* __restrict__ ctx) {
    const int b = blockIdx.x;
    const int tid = threadIdx.x;   // 256
    __shared__ float sm[256];
    const float* lg = g_logits + b * Tq;

    ctx[b * Dq + tid] = 0.f;
    ctx[b * Dq + 256 + tid] = 0.f;

    float mx = -1e30f;
    for (int t = tid; t < Tq; t += 256) mx = fmaxf(mx, lg[t]);
    sm[tid] = mx; __syncthreads();
    for (int s = 128; s > 0; s >>= 1) {
        if (tid < s) sm[tid] = fmaxf(sm[tid], sm[tid + s]);
        __syncthreads();
    }
    mx = sm[0]; __syncthreads();

    float sum = 0.f;
    for (int t = tid; t < Tq; t += 256) sum += expf(lg[t] - mx);
    sm[tid] = sum; __syncthreads();
    for (int s = 128; s > 0; s >>= 1) {
        if (tid < s) sm[tid] += sm[tid + s];
        __syncthreads();
    }
    float inv = 1.f / sm[0];

    for (int t = tid; t < Tq; t += 256)
        out_w[b * Tq + t] = expf(lg[t] - mx) * inv;
}

// ---------------------------------------------------------------------------
// Kernel 3: context[b,d] = sum_t w[b,t] * features[b,t,d]
// ---------------------------------------------------------------------------
#define TCHUNK 128
__global__ __launch_bounds__(256, 8)
void context_kernel(const float* __restrict__ features,
                    const float* __restrict__ w,
                    float* __restrict__ ctx) {
    __shared__ float ws[TCHUNK];
    const int b  = blockIdx.y;
    const int t0 = blockIdx.x * TCHUNK;
    const int tid = threadIdx.x;
    const int d4 = tid & 127;
    const int tp = tid >> 7;

    if (tid < TCHUNK) ws[tid] = w[b * Tq + t0 + tid];
    __syncthreads();

    const float* fb = features + (long)b * Tq * Dq + (long)t0 * Dq + d4 * 4;
    float4 acc = make_float4(0.f, 0.f, 0.f, 0.f);
    #pragma unroll 4
    for (int i = tp; i < TCHUNK; i += 2) {
        float  wt = ws[i];
        float4 v  = *reinterpret_cast<const float4*>(fb + (long)i * Dq);
        acc.x = fmaf(wt, v.x, acc.x);
        acc.y = fmaf(wt, v.y, acc.y);
        acc.z = fmaf(wt, v.z, acc.z);
        acc.w = fmaf(wt, v.w, acc.w);
    }
    float* dst = ctx + b * Dq + d4 * 4;
    atomicAdd(dst + 0, acc.x);
    atomicAdd(dst + 1, acc.y);
    atomicAdd(dst + 2, acc.z);
    atomicAdd(dst + 3, acc.w);
}

// ---------------------------------------------------------------------------
extern "C" void kernel_launch(void* const* d_in, const int* in_sizes, int n_in,
                              void* d_out, int out_size) {
    const float* features = (const float*)d_in[0];  // [B,T,D]
    const float* hidden   = (const float*)d_in[1];  // [B,H]
    const float* Wk       = (const float*)d_in[2];  // [D,U]
    const float* Wb       = (const float*)d_in[3];  // [U]
    const float* Uk       = (const float*)d_in[4];  // [H,U]
    const float* Ub       = (const float*)d_in[5];  // [U]
    const float* Vk       = (const float*)d_in[6];  // [U,1]
    // d_in[7] = Vb [1]: uniform logit shift -> softmax-invariant -> unused.

    float* out  = (float*)d_out;
    float* ctx  = out;               // context_vector [B, D]  (tuple output 0)
    float* attw = out + Bq * Dq;     // attention_weights [B, T, 1] (tuple output 1)

    cudaFuncSetAttribute(logits_kernel,
                         cudaFuncAttributeMaxDynamicSharedMemorySize, SM_TOT);

    uh_kernel<<<dim3(Uq / 128, Bq), 128>>>(hidden, Uk, Ub, Wb);
    wkh_kernel<<<dim3(16, 16), dim3(32, 8)>>>(Wk);
    logits_kernel<<<(Bq * Tq) / BM, 256, SM_TOT>>>(features, Vk);
    softmax_kernel<<<Bq, 256>>>(attw, ctx);
    context_kernel<<<dim3(Tq / TCHUNK, Bq), 256>>>(features, attw, ctx);
}